// round 1
// baseline (speedup 1.0000x reference)
#include <cuda_runtime.h>

// ---------------- problem constants ----------------
#define N_EC   100000
#define N_DG   400000
#define N_CA3  120000
#define N_CA1  100000
#define PP_NNZ 10000000
#define MF_NNZ 8000000
#define RC_NNZ 6000000
#define SC_NNZ 6000000
#define T_STEPS 4

// ---------------- persistent device state ----------------
__device__ float g_v_ec[N_EC],  g_u_ec[N_EC];
__device__ float g_v_dg[N_DG],  g_u_dg[N_DG];
__device__ float g_v_c3[N_CA3], g_u_c3[N_CA3];
__device__ float g_v_c1[N_CA1], g_u_c1[N_CA1];
__device__ float g_spk_ec[N_EC];
__device__ float g_spk_dg[N_DG];
__device__ float g_spk_c3[N_CA3];
__device__ float g_I_dg[N_DG];
__device__ float g_I_c3[N_CA3];
__device__ float g_I_c1[N_CA1];
__device__ float g_sum[3];     // [0]=dg input sum, [1]=ca3 input sum, [2]=ca1 input sum
__device__ int   g_flag[4];    // [0]=ec any-spike, [1]=dg, [2]=c3 parity0, [3]=c3 parity1
__device__ float g_iv[6];      // inhibitory LIF scalar state: pop*2 + parity (dg,c3,c1)

// ---------------- kernels ----------------
__global__ void init_kernel() {
    int i0 = blockIdx.x * blockDim.x + threadIdx.x;
    int st = gridDim.x * blockDim.x;
    for (int i = i0; i < N_DG;  i += st) { g_v_dg[i] = -65.f; g_u_dg[i] = -13.f; }
    for (int i = i0; i < N_CA3; i += st) { g_v_c3[i] = -65.f; g_u_c3[i] = -13.f; g_spk_c3[i] = 0.f; }
    for (int i = i0; i < N_EC;  i += st) { g_v_ec[i] = -65.f; g_u_ec[i] = -13.f; }
    for (int i = i0; i < N_CA1; i += st) { g_v_c1[i] = -65.f; g_u_c1[i] = -13.f; }
    if (i0 < 6) g_iv[i0] = 0.f;
    if (i0 < 4) g_flag[i0] = 0;
    if (i0 < 3) g_sum[i0] = 0.f;
}

// zero per-step accumulators. Preserves the c3 spike flag of the PREVIOUS step
// (slot (t+1)&1), which the recurrent-collateral transmit of this step reads.
__global__ void zero_kernel(int t) {
    int i0 = blockIdx.x * blockDim.x + threadIdx.x;
    int st = gridDim.x * blockDim.x;
    for (int i = i0; i < N_DG;  i += st) g_I_dg[i] = 0.f;
    for (int i = i0; i < N_CA3; i += st) g_I_c3[i] = 0.f;
    for (int i = i0; i < N_CA1; i += st) g_I_c1[i] = 0.f;
    if (i0 == 0) {
        g_sum[0] = 0.f; g_sum[1] = 0.f; g_sum[2] = 0.f;
        g_flag[0] = 0; g_flag[1] = 0;
        g_flag[2 + (t & 1)] = 0;   // slot ca3 will write this step
    }
}

// Izhikevich population update (+ optional scalar inhibitory LIF evaluated
// redundantly per-thread from the double-buffered scalar state; one thread
// commits the new LIF state).
__global__ void izh_kernel(float* __restrict__ v, float* __restrict__ u,
                           const float* __restrict__ c, const float* __restrict__ d,
                           const float* __restrict__ I, int n,
                           float* __restrict__ spk, int* __restrict__ flag,
                           const float* __restrict__ sum, float inv_n,
                           const float* __restrict__ iv_in, float* __restrict__ iv_out,
                           float* __restrict__ out)
{
    float inh = 0.f;
    if (sum) {
        float mean = (*sum) * inv_n;
        float ivn  = 0.9f * (*iv_in) + 0.1f * mean;  // TAU_I=0.9
        bool  si   = (ivn >= 1.0f);                   // THR_I=1.0
        inh        = si ? 2.0f : 0.0f;                // INH_GAIN=2.0
        if (blockIdx.x == 0 && threadIdx.x == 0)
            *iv_out = si ? 0.f : ivn;
    }
    bool any = false;
    for (int i = blockIdx.x * blockDim.x + threadIdx.x; i < n;
         i += gridDim.x * blockDim.x) {
        float vv = v[i], uu = u[i];
        float Ii = I[i] - inh;
        vv = vv + (0.04f * vv * vv + 5.0f * vv + 140.0f - uu + Ii) * 0.5f; // DT=0.5
        vv = fminf(fmaxf(vv, -90.f), 40.f);
        uu = uu + 0.01f * (0.2f * vv - uu);  // A*DT=0.01, B=0.2, uses post-clip v
        float sp = (vv >= 30.f) ? 1.f : 0.f;
        if (sp != 0.f) { vv = c[i]; uu += d[i]; any = true; }
        v[i] = vv; u[i] = uu;
        if (spk) spk[i] = sp;
        if (out) out[i] = vv;
    }
    if (flag && any) *flag = 1;   // racing same value: benign
}

// COO scatter: I[tgt[e]] += val[e]*spk[src[e]]; also reduces the total sum
// (for the inhibitory mean). Early-exits if the source population had no
// spikes this step, skipping ALL edge traffic.
__global__ void transmit_kernel(const int* __restrict__ src, const int* __restrict__ tgt,
                                const float* __restrict__ val, int nnz,
                                const float* __restrict__ spk,
                                float* __restrict__ I, float* __restrict__ sum,
                                const int* __restrict__ flag)
{
    if (*flag == 0) return;   // uniform across all threads
    float acc = 0.f;
    for (int e = blockIdx.x * blockDim.x + threadIdx.x; e < nnz;
         e += gridDim.x * blockDim.x) {
        int   sr = src[e];
        float s  = __ldg(&spk[sr]);
        if (s != 0.f) {
            float w = val[e] * s;
            atomicAdd(&I[tgt[e]], w);
            acc += w;
        }
    }
    // block reduction of acc -> single atomicAdd
    for (int o = 16; o > 0; o >>= 1) acc += __shfl_down_sync(0xffffffffu, acc, o);
    __shared__ float sh[8];
    int lane = threadIdx.x & 31, wid = threadIdx.x >> 5;
    if (lane == 0) sh[wid] = acc;
    __syncthreads();
    if (wid == 0) {
        acc = (lane < (int)(blockDim.x >> 5)) ? sh[lane] : 0.f;
        for (int o = 4; o > 0; o >>= 1) acc += __shfl_down_sync(0xffffffffu, acc, o);
        if (lane == 0 && acc != 0.f) atomicAdd(sum, acc);
    }
}

// ---------------- host ----------------
static void* symaddr(const void* s) {
    void* p = nullptr;
    cudaGetSymbolAddress(&p, s);
    return p;
}

extern "C" void kernel_launch(void* const* d_in, const int* in_sizes, int n_in,
                              void* d_out, int out_size)
{
    const float* drive  = (const float*)d_in[0];
    const int*   pp_src = (const int*)d_in[1];
    const int*   pp_tgt = (const int*)d_in[2];
    const float* pp_val = (const float*)d_in[3];
    const int*   mf_src = (const int*)d_in[4];
    const int*   mf_tgt = (const int*)d_in[5];
    const float* mf_val = (const float*)d_in[6];
    const int*   rc_src = (const int*)d_in[7];
    const int*   rc_tgt = (const int*)d_in[8];
    const float* rc_val = (const float*)d_in[9];
    const int*   sc_src = (const int*)d_in[10];
    const int*   sc_tgt = (const int*)d_in[11];
    const float* sc_val = (const float*)d_in[12];
    const float* ec_c = (const float*)d_in[13];
    const float* ec_d = (const float*)d_in[14];
    const float* dg_c = (const float*)d_in[15];
    const float* dg_d = (const float*)d_in[16];
    const float* c3_c = (const float*)d_in[17];
    const float* c3_d = (const float*)d_in[18];
    const float* c1_c = (const float*)d_in[19];
    const float* c1_d = (const float*)d_in[20];
    float* out = (float*)d_out;

    float* v_ec = (float*)symaddr(g_v_ec);  float* u_ec = (float*)symaddr(g_u_ec);
    float* v_dg = (float*)symaddr(g_v_dg);  float* u_dg = (float*)symaddr(g_u_dg);
    float* v_c3 = (float*)symaddr(g_v_c3);  float* u_c3 = (float*)symaddr(g_u_c3);
    float* v_c1 = (float*)symaddr(g_v_c1);  float* u_c1 = (float*)symaddr(g_u_c1);
    float* spk_ec = (float*)symaddr(g_spk_ec);
    float* spk_dg = (float*)symaddr(g_spk_dg);
    float* spk_c3 = (float*)symaddr(g_spk_c3);
    float* I_dg = (float*)symaddr(g_I_dg);
    float* I_c3 = (float*)symaddr(g_I_c3);
    float* I_c1 = (float*)symaddr(g_I_c1);
    float* sum  = (float*)symaddr(g_sum);
    int*   flag = (int*)symaddr(g_flag);
    float* iv   = (float*)symaddr(g_iv);

    const int TB = 256;
    const int TGRID = 2048;   // grid-stride; fast exit when flag==0

    init_kernel<<<512, TB>>>();

    for (int t = 0; t < T_STEPS; ++t) {
        int p  = t & 1;
        int pn = (t + 1) & 1;

        zero_kernel<<<512, TB>>>(t);

        // EC update (external drive, no inhibition)
        izh_kernel<<<(N_EC + TB - 1) / TB, TB>>>(
            v_ec, u_ec, ec_c, ec_d, drive + (size_t)t * N_EC, N_EC,
            spk_ec, flag + 0, nullptr, 0.f, nullptr, nullptr, nullptr);

        // CA3 recurrent collaterals (use previous step's c3 spikes/flag)
        transmit_kernel<<<TGRID, TB>>>(rc_src, rc_tgt, rc_val, RC_NNZ,
                                       spk_c3, I_c3, sum + 1, flag + 2 + pn);

        // Perforant path EC -> DG
        transmit_kernel<<<TGRID, TB>>>(pp_src, pp_tgt, pp_val, PP_NNZ,
                                       spk_ec, I_dg, sum + 0, flag + 0);

        // DG update (+ scalar inhibition from dg_I.mean())
        izh_kernel<<<(N_DG + TB - 1) / TB, TB>>>(
            v_dg, u_dg, dg_c, dg_d, I_dg, N_DG,
            spk_dg, flag + 1, sum + 0, 1.f / N_DG,
            iv + 0 + p, iv + 0 + pn, nullptr);

        // Mossy fibers DG -> CA3
        transmit_kernel<<<TGRID, TB>>>(mf_src, mf_tgt, mf_val, MF_NNZ,
                                       spk_dg, I_c3, sum + 1, flag + 1);

        // CA3 update
        izh_kernel<<<(N_CA3 + TB - 1) / TB, TB>>>(
            v_c3, u_c3, c3_c, c3_d, I_c3, N_CA3,
            spk_c3, flag + 2 + p, sum + 1, 1.f / N_CA3,
            iv + 2 + p, iv + 2 + pn, nullptr);

        // Schaffer collaterals CA3 -> CA1
        transmit_kernel<<<TGRID, TB>>>(sc_src, sc_tgt, sc_val, SC_NNZ,
                                       spk_c3, I_c1, sum + 2, flag + 2 + p);

        // CA1 update; final step writes membrane potential to d_out
        izh_kernel<<<(N_CA1 + TB - 1) / TB, TB>>>(
            v_c1, u_c1, c1_c, c1_d, I_c1, N_CA1,
            nullptr, nullptr, sum + 2, 1.f / N_CA1,
            iv + 4 + p, iv + 4 + pn,
            (t == T_STEPS - 1) ? out : nullptr);
    }
}